// round 10
// baseline (speedup 1.0000x reference)
#include <cuda_runtime.h>
#include <cuda_fp16.h>

#define NN 50000
#define EE 800000
#define INCH 128
#define C1 64
#define C2 32
#define SLOPE 0.2f
#define CAP 64          // padded CSR bucket capacity (max degree ~40 for Poisson(16))

// -------- device scratch --------
__device__ __align__(256) __half g_h1[NN * C1];
__device__ __align__(256) __half g_z1[NN * C1];   // layer1 output, fp16
__device__ __align__(256) __half g_h2[NN * C2];
__device__ float g_ls[NN];
__device__ float g_ld[NN];
__device__ int g_cnt[NN];                       // bucket cursor -> degree
__device__ __align__(256) int g_csr[NN * CAP];  // src node per slot

// ================= cursor zeroing (runs on side stream) =================
__global__ void zero_cnt_kernel() {
    int i = blockIdx.x * blockDim.x + threadIdx.x;
    if (i < NN) g_cnt[i] = 0;
}

// ================= padded-bucket scatter: 4 edges/thread, src only =================
__global__ __launch_bounds__(256) void scatter_kernel(
    const int4* __restrict__ src4, const int4* __restrict__ dst4)
{
    int i = blockIdx.x * blockDim.x + threadIdx.x;
    if (i >= EE / 4) return;
    int4 s4 = src4[i];
    int4 d4 = dst4[i];
    int i0 = atomicAdd(&g_cnt[d4.x], 1);
    int i1 = atomicAdd(&g_cnt[d4.y], 1);
    int i2 = atomicAdd(&g_cnt[d4.z], 1);
    int i3 = atomicAdd(&g_cnt[d4.w], 1);
    if (i0 < CAP) g_csr[d4.x * CAP + i0] = s4.x;
    if (i1 < CAP) g_csr[d4.y * CAP + i1] = s4.y;
    if (i2 < CAP) g_csr[d4.z * CAP + i2] = s4.z;
    if (i3 < CAP) g_csr[d4.w * CAP + i3] = s4.w;
}

// ================= layer1 projection =================
#define G1_XSTRIDE 132
#define G1_SMEM ((INCH * C1 + 128 * G1_XSTRIDE) * 4)
__global__ __launch_bounds__(512) void gemm1_kernel(
    const float* __restrict__ x, const float* __restrict__ W,
    const float* __restrict__ asrc, const float* __restrict__ adst)
{
    extern __shared__ float sm[];
    float* Ws = sm;
    float* xs = sm + INCH * C1;

    int tid = threadIdx.x;
    int tx = tid & 15;
    int ty = tid >> 4;
    int base = blockIdx.x * 128;

    const float4* W4 = (const float4*)W;
    float4* Ws4v = (float4*)Ws;
    #pragma unroll
    for (int i = tid; i < INCH * C1 / 4; i += 512) Ws4v[i] = W4[i];

    const float4* x4 = (const float4*)x;
    #pragma unroll
    for (int it = 0; it < 8; it++) {
        int f = it * 512 + tid;
        int n = f >> 5;
        int k4 = f & 31;
        float4 v = make_float4(0.f, 0.f, 0.f, 0.f);
        if (base + n < NN) v = x4[(size_t)(base + n) * 32 + k4];
        *(float4*)&xs[n * G1_XSTRIDE + k4 * 4] = v;
    }
    __syncthreads();

    float acc[4][4];
    #pragma unroll
    for (int i = 0; i < 4; i++)
        #pragma unroll
        for (int j = 0; j < 4; j++) acc[i][j] = 0.f;

    const float4* WsRow = (const float4*)Ws + tx;
    const float* xr0 = &xs[(ty * 4 + 0) * G1_XSTRIDE];
    const float* xr1 = &xs[(ty * 4 + 1) * G1_XSTRIDE];
    const float* xr2 = &xs[(ty * 4 + 2) * G1_XSTRIDE];
    const float* xr3 = &xs[(ty * 4 + 3) * G1_XSTRIDE];

    #pragma unroll 8
    for (int k = 0; k < INCH; k++) {
        float4 w = WsRow[k * 16];
        float x0 = xr0[k], x1 = xr1[k], x2 = xr2[k], x3 = xr3[k];
        acc[0][0] = fmaf(x0, w.x, acc[0][0]); acc[0][1] = fmaf(x0, w.y, acc[0][1]);
        acc[0][2] = fmaf(x0, w.z, acc[0][2]); acc[0][3] = fmaf(x0, w.w, acc[0][3]);
        acc[1][0] = fmaf(x1, w.x, acc[1][0]); acc[1][1] = fmaf(x1, w.y, acc[1][1]);
        acc[1][2] = fmaf(x1, w.z, acc[1][2]); acc[1][3] = fmaf(x1, w.w, acc[1][3]);
        acc[2][0] = fmaf(x2, w.x, acc[2][0]); acc[2][1] = fmaf(x2, w.y, acc[2][1]);
        acc[2][2] = fmaf(x2, w.z, acc[2][2]); acc[2][3] = fmaf(x2, w.w, acc[2][3]);
        acc[3][0] = fmaf(x3, w.x, acc[3][0]); acc[3][1] = fmaf(x3, w.y, acc[3][1]);
        acc[3][2] = fmaf(x3, w.z, acc[3][2]); acc[3][3] = fmaf(x3, w.w, acc[3][3]);
    }

    #pragma unroll
    for (int i = 0; i < 4; i++) {
        int node = base + ty * 4 + i;
        if (node < NN) {
            __half2 lo = __float22half2_rn(make_float2(acc[i][0], acc[i][1]));
            __half2 hi = __float22half2_rn(make_float2(acc[i][2], acc[i][3]));
            *(__half2*)&g_h1[(size_t)node * C1 + tx * 4 + 0] = lo;
            *(__half2*)&g_h1[(size_t)node * C1 + tx * 4 + 2] = hi;
        }
    }

    float as0 = asrc[tx * 4 + 0], as1 = asrc[tx * 4 + 1], as2 = asrc[tx * 4 + 2], as3 = asrc[tx * 4 + 3];
    float ad0 = adst[tx * 4 + 0], ad1 = adst[tx * 4 + 1], ad2 = adst[tx * 4 + 2], ad3 = adst[tx * 4 + 3];
    __syncthreads();
    float* redS = xs;
    float* redD = xs + 128 * 17;
    #pragma unroll
    for (int i = 0; i < 4; i++) {
        int nl = ty * 4 + i;
        float ps = acc[i][0] * as0 + acc[i][1] * as1 + acc[i][2] * as2 + acc[i][3] * as3;
        float pd = acc[i][0] * ad0 + acc[i][1] * ad1 + acc[i][2] * ad2 + acc[i][3] * ad3;
        redS[nl * 17 + tx] = ps;
        redD[nl * 17 + tx] = pd;
    }
    __syncthreads();
    if (tid < 128) {
        int node = base + tid;
        if (node < NN) {
            float s = 0.f, d = 0.f;
            #pragma unroll
            for (int t = 0; t < 16; t++) { s += redS[tid * 17 + t]; d += redD[tid * 17 + t]; }
            g_ls[node] = s;
            g_ld[node] = d;
        }
    }
}

// ================= layer1 gather-side aggregate -> z1 (fp16) =================
// Leader lane of each edge-group computes ev once; shfl-broadcast to the group.
__global__ __launch_bounds__(256) void agg1_kernel(const float* __restrict__ bias)
{
    const int TPE = C1 / 8;   // 8
    const int G = 32 / TPE;   // 4
    int warp = (blockIdx.x * blockDim.x + threadIdx.x) >> 5;
    if (warp >= NN) return;
    int lane = threadIdx.x & 31;
    int g = lane >> 3, t = lane & 7;
    int leader = lane & ~(TPE - 1);

    int beg = warp * CAP;
    int deg = g_cnt[warp];
    deg = deg < CAP ? deg : CAP;
    int end = beg + deg;
    float ldv = g_ld[warp];
    float acc[8];
    #pragma unroll
    for (int j = 0; j < 8; j++) acc[j] = 0.f;
    float den = 0.f;

    for (int base = beg; base < end; base += G) {
        int i = base + g;
        bool valid = i < end;
        int s = valid ? g_csr[i] : 0;
        float ev = 0.f;
        if (valid && t == 0) {
            float l = g_ls[s] + ldv;
            l = l > 0.f ? l : SLOPE * l;
            ev = __expf(l);
            den += ev;
        }
        ev = __shfl_sync(0xffffffffu, ev, leader);
        uint4 hv = make_uint4(0u, 0u, 0u, 0u);
        if (valid) hv = *(const uint4*)(g_h1 + (size_t)s * C1 + t * 8);
        const __half2* hp = (const __half2*)&hv;
        #pragma unroll
        for (int j = 0; j < 4; j++) {
            float2 f = __half22float2(hp[j]);
            acc[2 * j + 0] = fmaf(f.x, ev, acc[2 * j + 0]);
            acc[2 * j + 1] = fmaf(f.y, ev, acc[2 * j + 1]);
        }
    }

    #pragma unroll
    for (int off = TPE; off < 32; off <<= 1) {
        den += __shfl_xor_sync(0xffffffffu, den, off);
        #pragma unroll
        for (int j = 0; j < 8; j++) acc[j] += __shfl_xor_sync(0xffffffffu, acc[j], off);
    }
    den = __shfl_sync(0xffffffffu, den, 0);   // full den lives on t==0 lanes

    if (g == 0) {
        float inv = den > 0.f ? 1.f / den : 0.f;
        __half2 o[4];
        #pragma unroll
        for (int j = 0; j < 4; j++) {
            float a = fmaxf(acc[2 * j + 0] * inv + bias[t * 8 + 2 * j + 0], 0.f);
            float b = fmaxf(acc[2 * j + 1] * inv + bias[t * 8 + 2 * j + 1], 0.f);
            o[j] = __float22half2_rn(make_float2(a, b));
        }
        *(uint4*)&g_z1[(size_t)warp * C1 + t * 8] = *(uint4*)o;
    }
}

// ================= layer2 projection: 4 nodes x 4 ch per thread =================
#define G2_XSTRIDE 68
__global__ __launch_bounds__(256) void gemm2_kernel(
    const float* __restrict__ W,
    const float* __restrict__ asrc, const float* __restrict__ adst)
{
    __shared__ float Ws[C1 * C2];
    __shared__ float xs[128 * G2_XSTRIDE];

    int tid = threadIdx.x;
    int tx = tid & 7;
    int ty = tid >> 3;
    int base = blockIdx.x * 128;

    for (int i = tid; i < C1 * C2; i += 256) Ws[i] = W[i];

    const uint4* z4 = (const uint4*)g_z1;
    #pragma unroll
    for (int it = 0; it < 4; it++) {
        int f = it * 256 + tid;
        int n = f >> 3, k8 = f & 7;
        int node = base + n;
        uint4 hv = make_uint4(0u, 0u, 0u, 0u);
        if (node < NN) hv = z4[(size_t)node * 8 + k8];
        const __half2* hp = (const __half2*)&hv;
        float* dstp = &xs[n * G2_XSTRIDE + k8 * 8];
        #pragma unroll
        for (int j = 0; j < 4; j++) {
            float2 f2 = __half22float2(hp[j]);
            dstp[2 * j + 0] = f2.x;
            dstp[2 * j + 1] = f2.y;
        }
    }
    __syncthreads();

    float acc[4][4];
    #pragma unroll
    for (int i = 0; i < 4; i++)
        #pragma unroll
        for (int j = 0; j < 4; j++) acc[i][j] = 0.f;

    const float4* WsRow = (const float4*)Ws + tx;
    const float* xr0 = &xs[(ty * 4 + 0) * G2_XSTRIDE];
    const float* xr1 = &xs[(ty * 4 + 1) * G2_XSTRIDE];
    const float* xr2 = &xs[(ty * 4 + 2) * G2_XSTRIDE];
    const float* xr3 = &xs[(ty * 4 + 3) * G2_XSTRIDE];

    #pragma unroll 8
    for (int k = 0; k < C1; k++) {
        float4 w = WsRow[k * 8];
        float x0 = xr0[k], x1 = xr1[k], x2 = xr2[k], x3 = xr3[k];
        acc[0][0] = fmaf(x0, w.x, acc[0][0]); acc[0][1] = fmaf(x0, w.y, acc[0][1]);
        acc[0][2] = fmaf(x0, w.z, acc[0][2]); acc[0][3] = fmaf(x0, w.w, acc[0][3]);
        acc[1][0] = fmaf(x1, w.x, acc[1][0]); acc[1][1] = fmaf(x1, w.y, acc[1][1]);
        acc[1][2] = fmaf(x1, w.z, acc[1][2]); acc[1][3] = fmaf(x1, w.w, acc[1][3]);
        acc[2][0] = fmaf(x2, w.x, acc[2][0]); acc[2][1] = fmaf(x2, w.y, acc[2][1]);
        acc[2][2] = fmaf(x2, w.z, acc[2][2]); acc[2][3] = fmaf(x2, w.w, acc[2][3]);
        acc[3][0] = fmaf(x3, w.x, acc[3][0]); acc[3][1] = fmaf(x3, w.y, acc[3][1]);
        acc[3][2] = fmaf(x3, w.z, acc[3][2]); acc[3][3] = fmaf(x3, w.w, acc[3][3]);
    }

    #pragma unroll
    for (int i = 0; i < 4; i++) {
        int node = base + ty * 4 + i;
        if (node < NN) {
            __half2 lo = __float22half2_rn(make_float2(acc[i][0], acc[i][1]));
            __half2 hi = __float22half2_rn(make_float2(acc[i][2], acc[i][3]));
            *(__half2*)&g_h2[(size_t)node * C2 + tx * 4 + 0] = lo;
            *(__half2*)&g_h2[(size_t)node * C2 + tx * 4 + 2] = hi;
        }
    }

    float as0 = asrc[tx * 4 + 0], as1 = asrc[tx * 4 + 1], as2 = asrc[tx * 4 + 2], as3 = asrc[tx * 4 + 3];
    float ad0 = adst[tx * 4 + 0], ad1 = adst[tx * 4 + 1], ad2 = adst[tx * 4 + 2], ad3 = adst[tx * 4 + 3];
    __syncthreads();
    float* redS = xs;
    float* redD = xs + 128 * 9;
    #pragma unroll
    for (int i = 0; i < 4; i++) {
        int nl = ty * 4 + i;
        float ps = acc[i][0] * as0 + acc[i][1] * as1 + acc[i][2] * as2 + acc[i][3] * as3;
        float pd = acc[i][0] * ad0 + acc[i][1] * ad1 + acc[i][2] * ad2 + acc[i][3] * ad3;
        redS[nl * 9 + tx] = ps;
        redD[nl * 9 + tx] = pd;
    }
    __syncthreads();
    if (tid < 128) {
        int node = base + tid;
        if (node < NN) {
            float s = 0.f, d = 0.f;
            #pragma unroll
            for (int t = 0; t < 8; t++) { s += redS[tid * 9 + t]; d += redD[tid * 9 + t]; }
            g_ls[node] = s;
            g_ld[node] = d;
        }
    }
}

// ================= layer2 gather-side aggregate -> output =================
__global__ __launch_bounds__(256) void agg2_kernel(
    const float* __restrict__ bias, float* __restrict__ out)
{
    const int TPE = C2 / 8;   // 4
    const int G = 32 / TPE;   // 8
    int warp = (blockIdx.x * blockDim.x + threadIdx.x) >> 5;
    if (warp >= NN) return;
    int lane = threadIdx.x & 31;
    int g = lane / TPE, t = lane % TPE;
    int leader = lane & ~(TPE - 1);

    int beg = warp * CAP;
    int deg = g_cnt[warp];
    deg = deg < CAP ? deg : CAP;
    int end = beg + deg;
    float ldv = g_ld[warp];
    float acc[8];
    #pragma unroll
    for (int j = 0; j < 8; j++) acc[j] = 0.f;
    float den = 0.f;

    for (int base = beg; base < end; base += G) {
        int i = base + g;
        bool valid = i < end;
        int s = valid ? g_csr[i] : 0;
        float ev = 0.f;
        if (valid && t == 0) {
            float l = g_ls[s] + ldv;
            l = l > 0.f ? l : SLOPE * l;
            ev = __expf(l);
            den += ev;
        }
        ev = __shfl_sync(0xffffffffu, ev, leader);
        uint4 hv = make_uint4(0u, 0u, 0u, 0u);
        if (valid) hv = *(const uint4*)(g_h2 + (size_t)s * C2 + t * 8);
        const __half2* hp = (const __half2*)&hv;
        #pragma unroll
        for (int j = 0; j < 4; j++) {
            float2 f = __half22float2(hp[j]);
            acc[2 * j + 0] = fmaf(f.x, ev, acc[2 * j + 0]);
            acc[2 * j + 1] = fmaf(f.y, ev, acc[2 * j + 1]);
        }
    }

    #pragma unroll
    for (int off = TPE; off < 32; off <<= 1) {
        den += __shfl_xor_sync(0xffffffffu, den, off);
        #pragma unroll
        for (int j = 0; j < 8; j++) acc[j] += __shfl_xor_sync(0xffffffffu, acc[j], off);
    }
    den = __shfl_sync(0xffffffffu, den, 0);

    if (g == 0) {
        float inv = den > 0.f ? 1.f / den : 0.f;
        float4 v0, v1;
        v0.x = acc[0] * inv + bias[t * 8 + 0];
        v0.y = acc[1] * inv + bias[t * 8 + 1];
        v0.z = acc[2] * inv + bias[t * 8 + 2];
        v0.w = acc[3] * inv + bias[t * 8 + 3];
        v1.x = acc[4] * inv + bias[t * 8 + 4];
        v1.y = acc[5] * inv + bias[t * 8 + 5];
        v1.z = acc[6] * inv + bias[t * 8 + 6];
        v1.w = acc[7] * inv + bias[t * 8 + 7];
        *(float4*)&out[(size_t)warp * C2 + t * 8 + 0] = v0;
        *(float4*)&out[(size_t)warp * C2 + t * 8 + 4] = v1;
    }
}

extern "C" void kernel_launch(void* const* d_in, const int* in_sizes, int n_in,
                              void* d_out, int out_size)
{
    const float* x   = (const float*)d_in[0];
    const int*   ei  = (const int*)d_in[1];
    const float* W1  = (const float*)d_in[2];
    const float* as1 = (const float*)d_in[3];
    const float* ad1 = (const float*)d_in[4];
    const float* b1  = (const float*)d_in[5];
    const float* W2  = (const float*)d_in[6];
    const float* as2 = (const float*)d_in[7];
    const float* ad2 = (const float*)d_in[8];
    const float* b2  = (const float*)d_in[9];
    const int* src = ei;
    const int* dst = ei + EE;

    static cudaStream_t s2 = nullptr;
    static cudaEvent_t evFork = nullptr, evJoin = nullptr;
    if (!s2) {
        cudaStreamCreateWithFlags(&s2, cudaStreamNonBlocking);
        cudaEventCreateWithFlags(&evFork, cudaEventDisableTiming);
        cudaEventCreateWithFlags(&evJoin, cudaEventDisableTiming);
        cudaFuncSetAttribute(gemm1_kernel, cudaFuncAttributeMaxDynamicSharedMemorySize, G1_SMEM);
    }

    const int T = 256;

    // fork: CSR build on s2 (independent of gemm1)
    cudaEventRecord(evFork, 0);
    cudaStreamWaitEvent(s2, evFork, 0);
    zero_cnt_kernel<<<(NN + 1023) / 1024, 1024, 0, s2>>>();
    scatter_kernel<<<(EE / 4 + T - 1) / T, T, 0, s2>>>((const int4*)src, (const int4*)dst);
    cudaEventRecord(evJoin, s2);

    // main stream: layer1 projection overlaps CSR build
    gemm1_kernel<<<(NN + 127) / 128, 512, G1_SMEM>>>(x, W1, as1, ad1);

    // join: aggregate needs both gemm1 outputs and the CSR
    cudaStreamWaitEvent(0, evJoin, 0);
    agg1_kernel<<<(NN * 32 + T - 1) / T, T>>>(b1);
    gemm2_kernel<<<(NN + 127) / 128, T>>>(W2, as2, ad2);
    agg2_kernel<<<(NN * 32 + T - 1) / T, T>>>(b2, (float*)d_out);
}

// round 11
// speedup vs baseline: 1.0251x; 1.0251x over previous
#include <cuda_runtime.h>
#include <cuda_fp16.h>

#define NN 50000
#define EE 800000
#define INCH 128
#define C1 64
#define C2 32
#define SLOPE 0.2f
#define CAP 64          // padded CSR bucket capacity (max degree ~40 for Poisson(16))

typedef unsigned long long ull;

// -------- device scratch --------
__device__ __align__(256) float g_h1[NN * C1];    // fp32 (converts were the alu bottleneck)
__device__ __align__(256) __half g_z1[NN * C1];   // layer1 output, fp16 (streamed coalesced)
__device__ __align__(256) float g_h2[NN * C2];    // fp32
__device__ float g_ls[NN];
__device__ float g_ld[NN];
__device__ int g_cnt[NN];                       // bucket cursor -> degree
__device__ __align__(256) int g_csr[NN * CAP];  // src node per slot

// -------- packed f32x2 helpers (sm_103a) --------
__device__ __forceinline__ ull pack2(float v) {
    ull r;
    asm("mov.b64 %0, {%1, %1};" : "=l"(r) : "f"(v));
    return r;
}
__device__ __forceinline__ void fma2(ull& acc, ull h, ull ev2) {
    asm("fma.rn.f32x2 %0, %1, %2, %0;" : "+l"(acc) : "l"(h), "l"(ev2));
}
__device__ __forceinline__ ull add2(ull a, ull b) {
    ull r;
    asm("add.rn.f32x2 %0, %1, %2;" : "=l"(r) : "l"(a), "l"(b));
    return r;
}
__device__ __forceinline__ float2 unpack2(ull v) {
    float2 f;
    asm("mov.b64 {%0, %1}, %2;" : "=f"(f.x), "=f"(f.y) : "l"(v));
    return f;
}

// ================= cursor zeroing (side stream) =================
__global__ void zero_cnt_kernel() {
    int i = blockIdx.x * blockDim.x + threadIdx.x;
    if (i < NN) g_cnt[i] = 0;
}

// ================= padded-bucket scatter: 4 edges/thread =================
__global__ __launch_bounds__(256) void scatter_kernel(
    const int4* __restrict__ src4, const int4* __restrict__ dst4)
{
    int i = blockIdx.x * blockDim.x + threadIdx.x;
    if (i >= EE / 4) return;
    int4 s4 = src4[i];
    int4 d4 = dst4[i];
    int i0 = atomicAdd(&g_cnt[d4.x], 1);
    int i1 = atomicAdd(&g_cnt[d4.y], 1);
    int i2 = atomicAdd(&g_cnt[d4.z], 1);
    int i3 = atomicAdd(&g_cnt[d4.w], 1);
    if (i0 < CAP) g_csr[d4.x * CAP + i0] = s4.x;
    if (i1 < CAP) g_csr[d4.y * CAP + i1] = s4.y;
    if (i2 < CAP) g_csr[d4.z * CAP + i2] = s4.z;
    if (i3 < CAP) g_csr[d4.w * CAP + i3] = s4.w;
}

// ================= layer1 projection =================
#define G1_XSTRIDE 132
#define G1_SMEM ((INCH * C1 + 128 * G1_XSTRIDE) * 4)
__global__ __launch_bounds__(512) void gemm1_kernel(
    const float* __restrict__ x, const float* __restrict__ W,
    const float* __restrict__ asrc, const float* __restrict__ adst)
{
    extern __shared__ float sm[];
    float* Ws = sm;
    float* xs = sm + INCH * C1;

    int tid = threadIdx.x;
    int tx = tid & 15;
    int ty = tid >> 4;
    int base = blockIdx.x * 128;

    const float4* W4 = (const float4*)W;
    float4* Ws4v = (float4*)Ws;
    #pragma unroll
    for (int i = tid; i < INCH * C1 / 4; i += 512) Ws4v[i] = W4[i];

    const float4* x4 = (const float4*)x;
    #pragma unroll
    for (int it = 0; it < 8; it++) {
        int f = it * 512 + tid;
        int n = f >> 5;
        int k4 = f & 31;
        float4 v = make_float4(0.f, 0.f, 0.f, 0.f);
        if (base + n < NN) v = x4[(size_t)(base + n) * 32 + k4];
        *(float4*)&xs[n * G1_XSTRIDE + k4 * 4] = v;
    }
    __syncthreads();

    float acc[4][4];
    #pragma unroll
    for (int i = 0; i < 4; i++)
        #pragma unroll
        for (int j = 0; j < 4; j++) acc[i][j] = 0.f;

    const float4* WsRow = (const float4*)Ws + tx;
    const float* xr0 = &xs[(ty * 4 + 0) * G1_XSTRIDE];
    const float* xr1 = &xs[(ty * 4 + 1) * G1_XSTRIDE];
    const float* xr2 = &xs[(ty * 4 + 2) * G1_XSTRIDE];
    const float* xr3 = &xs[(ty * 4 + 3) * G1_XSTRIDE];

    #pragma unroll 8
    for (int k = 0; k < INCH; k++) {
        float4 w = WsRow[k * 16];
        float x0 = xr0[k], x1 = xr1[k], x2 = xr2[k], x3 = xr3[k];
        acc[0][0] = fmaf(x0, w.x, acc[0][0]); acc[0][1] = fmaf(x0, w.y, acc[0][1]);
        acc[0][2] = fmaf(x0, w.z, acc[0][2]); acc[0][3] = fmaf(x0, w.w, acc[0][3]);
        acc[1][0] = fmaf(x1, w.x, acc[1][0]); acc[1][1] = fmaf(x1, w.y, acc[1][1]);
        acc[1][2] = fmaf(x1, w.z, acc[1][2]); acc[1][3] = fmaf(x1, w.w, acc[1][3]);
        acc[2][0] = fmaf(x2, w.x, acc[2][0]); acc[2][1] = fmaf(x2, w.y, acc[2][1]);
        acc[2][2] = fmaf(x2, w.z, acc[2][2]); acc[2][3] = fmaf(x2, w.w, acc[2][3]);
        acc[3][0] = fmaf(x3, w.x, acc[3][0]); acc[3][1] = fmaf(x3, w.y, acc[3][1]);
        acc[3][2] = fmaf(x3, w.z, acc[3][2]); acc[3][3] = fmaf(x3, w.w, acc[3][3]);
    }

    #pragma unroll
    for (int i = 0; i < 4; i++) {
        int node = base + ty * 4 + i;
        if (node < NN)
            *(float4*)&g_h1[(size_t)node * C1 + tx * 4] =
                make_float4(acc[i][0], acc[i][1], acc[i][2], acc[i][3]);
    }

    float as0 = asrc[tx * 4 + 0], as1 = asrc[tx * 4 + 1], as2 = asrc[tx * 4 + 2], as3 = asrc[tx * 4 + 3];
    float ad0 = adst[tx * 4 + 0], ad1 = adst[tx * 4 + 1], ad2 = adst[tx * 4 + 2], ad3 = adst[tx * 4 + 3];
    __syncthreads();
    float* redS = xs;
    float* redD = xs + 128 * 17;
    #pragma unroll
    for (int i = 0; i < 4; i++) {
        int nl = ty * 4 + i;
        float ps = acc[i][0] * as0 + acc[i][1] * as1 + acc[i][2] * as2 + acc[i][3] * as3;
        float pd = acc[i][0] * ad0 + acc[i][1] * ad1 + acc[i][2] * ad2 + acc[i][3] * ad3;
        redS[nl * 17 + tx] = ps;
        redD[nl * 17 + tx] = pd;
    }
    __syncthreads();
    if (tid < 128) {
        int node = base + tid;
        if (node < NN) {
            float s = 0.f, d = 0.f;
            #pragma unroll
            for (int t = 0; t < 16; t++) { s += redS[tid * 17 + t]; d += redD[tid * 17 + t]; }
            g_ls[node] = s;
            g_ld[node] = d;
        }
    }
}

// ================= layer1 aggregate (fp32 h, f32x2 math) -> z1 fp16 =================
__global__ __launch_bounds__(256) void agg1_kernel(const float* __restrict__ bias)
{
    const int TPE = 8;        // lanes per edge, 32B (8 fp32 ch) each
    const int G = 4;          // edge groups per warp
    int warp = (blockIdx.x * blockDim.x + threadIdx.x) >> 5;
    if (warp >= NN) return;
    int lane = threadIdx.x & 31;
    int g = lane >> 3, t = lane & 7;

    int beg = warp * CAP;
    int deg = g_cnt[warp];
    deg = deg < CAP ? deg : CAP;
    int end = beg + deg;
    float ldv = g_ld[warp];
    ull acc[4] = {0ull, 0ull, 0ull, 0ull};
    float den = 0.f;

    for (int base = beg; base < end; base += G) {
        int i = base + g;
        float ev = 0.f;
        ull h0 = 0, h1v = 0, h2v = 0, h3v = 0;
        if (i < end) {
            int s = g_csr[i];
            float l = g_ls[s] + ldv;
            l = l > 0.f ? l : SLOPE * l;
            ev = __expf(l);
            const ulonglong2* hp = (const ulonglong2*)(g_h1 + (size_t)s * C1 + t * 8);
            ulonglong2 A = hp[0], B = hp[1];
            h0 = A.x; h1v = A.y; h2v = B.x; h3v = B.y;
        }
        den += ev;
        ull ev2 = pack2(ev);
        fma2(acc[0], h0, ev2);
        fma2(acc[1], h1v, ev2);
        fma2(acc[2], h2v, ev2);
        fma2(acc[3], h3v, ev2);
    }

    #pragma unroll
    for (int off = TPE; off < 32; off <<= 1) {
        den += __shfl_xor_sync(0xffffffffu, den, off);
        #pragma unroll
        for (int j = 0; j < 4; j++)
            acc[j] = add2(acc[j], __shfl_xor_sync(0xffffffffu, acc[j], off));
    }

    if (g == 0) {
        float inv = den > 0.f ? 1.f / den : 0.f;
        __half2 o[4];
        #pragma unroll
        for (int j = 0; j < 4; j++) {
            float2 f = unpack2(acc[j]);
            float a = fmaxf(f.x * inv + bias[t * 8 + 2 * j + 0], 0.f);
            float b = fmaxf(f.y * inv + bias[t * 8 + 2 * j + 1], 0.f);
            o[j] = __float22half2_rn(make_float2(a, b));
        }
        *(uint4*)&g_z1[(size_t)warp * C1 + t * 8] = *(uint4*)o;
    }
}

// ================= layer2 projection: 4 nodes x 4 ch per thread =================
#define G2_XSTRIDE 68
__global__ __launch_bounds__(256) void gemm2_kernel(
    const float* __restrict__ W,
    const float* __restrict__ asrc, const float* __restrict__ adst)
{
    __shared__ float Ws[C1 * C2];
    __shared__ float xs[128 * G2_XSTRIDE];

    int tid = threadIdx.x;
    int tx = tid & 7;
    int ty = tid >> 3;
    int base = blockIdx.x * 128;

    for (int i = tid; i < C1 * C2; i += 256) Ws[i] = W[i];

    const uint4* z4 = (const uint4*)g_z1;
    #pragma unroll
    for (int it = 0; it < 4; it++) {
        int f = it * 256 + tid;
        int n = f >> 3, k8 = f & 7;
        int node = base + n;
        uint4 hv = make_uint4(0u, 0u, 0u, 0u);
        if (node < NN) hv = z4[(size_t)node * 8 + k8];
        const __half2* hp = (const __half2*)&hv;
        float* dstp = &xs[n * G2_XSTRIDE + k8 * 8];
        #pragma unroll
        for (int j = 0; j < 4; j++) {
            float2 f2 = __half22float2(hp[j]);
            dstp[2 * j + 0] = f2.x;
            dstp[2 * j + 1] = f2.y;
        }
    }
    __syncthreads();

    float acc[4][4];
    #pragma unroll
    for (int i = 0; i < 4; i++)
        #pragma unroll
        for (int j = 0; j < 4; j++) acc[i][j] = 0.f;

    const float4* WsRow = (const float4*)Ws + tx;
    const float* xr0 = &xs[(ty * 4 + 0) * G2_XSTRIDE];
    const float* xr1 = &xs[(ty * 4 + 1) * G2_XSTRIDE];
    const float* xr2 = &xs[(ty * 4 + 2) * G2_XSTRIDE];
    const float* xr3 = &xs[(ty * 4 + 3) * G2_XSTRIDE];

    #pragma unroll 8
    for (int k = 0; k < C1; k++) {
        float4 w = WsRow[k * 8];
        float x0 = xr0[k], x1 = xr1[k], x2 = xr2[k], x3 = xr3[k];
        acc[0][0] = fmaf(x0, w.x, acc[0][0]); acc[0][1] = fmaf(x0, w.y, acc[0][1]);
        acc[0][2] = fmaf(x0, w.z, acc[0][2]); acc[0][3] = fmaf(x0, w.w, acc[0][3]);
        acc[1][0] = fmaf(x1, w.x, acc[1][0]); acc[1][1] = fmaf(x1, w.y, acc[1][1]);
        acc[1][2] = fmaf(x1, w.z, acc[1][2]); acc[1][3] = fmaf(x1, w.w, acc[1][3]);
        acc[2][0] = fmaf(x2, w.x, acc[2][0]); acc[2][1] = fmaf(x2, w.y, acc[2][1]);
        acc[2][2] = fmaf(x2, w.z, acc[2][2]); acc[2][3] = fmaf(x2, w.w, acc[2][3]);
        acc[3][0] = fmaf(x3, w.x, acc[3][0]); acc[3][1] = fmaf(x3, w.y, acc[3][1]);
        acc[3][2] = fmaf(x3, w.z, acc[3][2]); acc[3][3] = fmaf(x3, w.w, acc[3][3]);
    }

    #pragma unroll
    for (int i = 0; i < 4; i++) {
        int node = base + ty * 4 + i;
        if (node < NN)
            *(float4*)&g_h2[(size_t)node * C2 + tx * 4] =
                make_float4(acc[i][0], acc[i][1], acc[i][2], acc[i][3]);
    }

    float as0 = asrc[tx * 4 + 0], as1 = asrc[tx * 4 + 1], as2 = asrc[tx * 4 + 2], as3 = asrc[tx * 4 + 3];
    float ad0 = adst[tx * 4 + 0], ad1 = adst[tx * 4 + 1], ad2 = adst[tx * 4 + 2], ad3 = adst[tx * 4 + 3];
    __syncthreads();
    float* redS = xs;
    float* redD = xs + 128 * 9;
    #pragma unroll
    for (int i = 0; i < 4; i++) {
        int nl = ty * 4 + i;
        float ps = acc[i][0] * as0 + acc[i][1] * as1 + acc[i][2] * as2 + acc[i][3] * as3;
        float pd = acc[i][0] * ad0 + acc[i][1] * ad1 + acc[i][2] * ad2 + acc[i][3] * ad3;
        redS[nl * 9 + tx] = ps;
        redD[nl * 9 + tx] = pd;
    }
    __syncthreads();
    if (tid < 128) {
        int node = base + tid;
        if (node < NN) {
            float s = 0.f, d = 0.f;
            #pragma unroll
            for (int t = 0; t < 8; t++) { s += redS[tid * 9 + t]; d += redD[tid * 9 + t]; }
            g_ls[node] = s;
            g_ld[node] = d;
        }
    }
}

// ================= layer2 aggregate (fp32 h, f32x2 math) -> output =================
__global__ __launch_bounds__(256) void agg2_kernel(
    const float* __restrict__ bias, float* __restrict__ out)
{
    const int TPE = 4;        // lanes per edge, 32B (8 fp32 ch) each
    const int G = 8;          // edge groups per warp
    int warp = (blockIdx.x * blockDim.x + threadIdx.x) >> 5;
    if (warp >= NN) return;
    int lane = threadIdx.x & 31;
    int g = lane >> 2, t = lane & 3;

    int beg = warp * CAP;
    int deg = g_cnt[warp];
    deg = deg < CAP ? deg : CAP;
    int end = beg + deg;
    float ldv = g_ld[warp];
    ull acc[4] = {0ull, 0ull, 0ull, 0ull};
    float den = 0.f;

    for (int base = beg; base < end; base += G) {
        int i = base + g;
        float ev = 0.f;
        ull h0 = 0, h1v = 0, h2v = 0, h3v = 0;
        if (i < end) {
            int s = g_csr[i];
            float l = g_ls[s] + ldv;
            l = l > 0.f ? l : SLOPE * l;
            ev = __expf(l);
            const ulonglong2* hp = (const ulonglong2*)(g_h2 + (size_t)s * C2 + t * 8);
            ulonglong2 A = hp[0], B = hp[1];
            h0 = A.x; h1v = A.y; h2v = B.x; h3v = B.y;
        }
        den += ev;
        ull ev2 = pack2(ev);
        fma2(acc[0], h0, ev2);
        fma2(acc[1], h1v, ev2);
        fma2(acc[2], h2v, ev2);
        fma2(acc[3], h3v, ev2);
    }

    #pragma unroll
    for (int off = TPE; off < 32; off <<= 1) {
        den += __shfl_xor_sync(0xffffffffu, den, off);
        #pragma unroll
        for (int j = 0; j < 4; j++)
            acc[j] = add2(acc[j], __shfl_xor_sync(0xffffffffu, acc[j], off));
    }

    if (g == 0) {
        float inv = den > 0.f ? 1.f / den : 0.f;
        float2 f0 = unpack2(acc[0]), f1 = unpack2(acc[1]);
        float2 f2 = unpack2(acc[2]), f3 = unpack2(acc[3]);
        float4 v0, v1;
        v0.x = f0.x * inv + bias[t * 8 + 0];
        v0.y = f0.y * inv + bias[t * 8 + 1];
        v0.z = f1.x * inv + bias[t * 8 + 2];
        v0.w = f1.y * inv + bias[t * 8 + 3];
        v1.x = f2.x * inv + bias[t * 8 + 4];
        v1.y = f2.y * inv + bias[t * 8 + 5];
        v1.z = f3.x * inv + bias[t * 8 + 6];
        v1.w = f3.y * inv + bias[t * 8 + 7];
        *(float4*)&out[(size_t)warp * C2 + t * 8 + 0] = v0;
        *(float4*)&out[(size_t)warp * C2 + t * 8 + 4] = v1;
    }
}

extern "C" void kernel_launch(void* const* d_in, const int* in_sizes, int n_in,
                              void* d_out, int out_size)
{
    const float* x   = (const float*)d_in[0];
    const int*   ei  = (const int*)d_in[1];
    const float* W1  = (const float*)d_in[2];
    const float* as1 = (const float*)d_in[3];
    const float* ad1 = (const float*)d_in[4];
    const float* b1  = (const float*)d_in[5];
    const float* W2  = (const float*)d_in[6];
    const float* as2 = (const float*)d_in[7];
    const float* ad2 = (const float*)d_in[8];
    const float* b2  = (const float*)d_in[9];
    const int* src = ei;
    const int* dst = ei + EE;

    static cudaStream_t s2 = nullptr;
    static cudaEvent_t evFork = nullptr, evJoin = nullptr;
    if (!s2) {
        cudaStreamCreateWithFlags(&s2, cudaStreamNonBlocking);
        cudaEventCreateWithFlags(&evFork, cudaEventDisableTiming);
        cudaEventCreateWithFlags(&evJoin, cudaEventDisableTiming);
        cudaFuncSetAttribute(gemm1_kernel, cudaFuncAttributeMaxDynamicSharedMemorySize, G1_SMEM);
    }

    const int T = 256;

    // fork: CSR build on s2 (independent of gemm1)
    cudaEventRecord(evFork, 0);
    cudaStreamWaitEvent(s2, evFork, 0);
    zero_cnt_kernel<<<(NN + 1023) / 1024, 1024, 0, s2>>>();
    scatter_kernel<<<(EE / 4 + T - 1) / T, T, 0, s2>>>((const int4*)src, (const int4*)dst);
    cudaEventRecord(evJoin, s2);

    // main stream: layer1 projection overlaps CSR build
    gemm1_kernel<<<(NN + 127) / 128, 512, G1_SMEM>>>(x, W1, as1, ad1);

    // join: aggregate needs both gemm1 outputs and the CSR
    cudaStreamWaitEvent(0, evJoin, 0);
    agg1_kernel<<<(NN * 32 + T - 1) / T, T>>>(b1);
    gemm2_kernel<<<(NN + 127) / 128, T>>>(W2, as2, ad2);
    agg2_kernel<<<(NN * 32 + T - 1) / T, T>>>(b2, (float*)d_out);
}

// round 12
// speedup vs baseline: 1.0522x; 1.0264x over previous
#include <cuda_runtime.h>
#include <cuda_fp16.h>

#define NN 50000
#define EE 800000
#define INCH 128
#define C1 64
#define C2 32
#define SLOPE 0.2f
#define CAP 64          // padded CSR bucket capacity (max degree ~40 for Poisson(16))

typedef unsigned long long ull;

// -------- device scratch --------
__device__ __align__(256) float g_h1[NN * C1];
__device__ __align__(256) __half g_z1[NN * C1];   // layer1 output, fp16 (streamed coalesced)
__device__ __align__(256) float g_h2[NN * C2];
__device__ float g_ls[NN];
__device__ float g_ld[NN];
__device__ int g_cnt[NN];                       // bucket cursor -> degree
__device__ __align__(256) int g_csr[NN * CAP];  // src node per slot

// -------- packed f32x2 helpers (sm_103a) --------
__device__ __forceinline__ ull pack2(float v) {
    ull r;
    asm("mov.b64 %0, {%1, %1};" : "=l"(r) : "f"(v));
    return r;
}
__device__ __forceinline__ void fma2(ull& acc, ull h, ull ev2) {
    asm("fma.rn.f32x2 %0, %1, %2, %0;" : "+l"(acc) : "l"(h), "l"(ev2));
}
__device__ __forceinline__ ull add2(ull a, ull b) {
    ull r;
    asm("add.rn.f32x2 %0, %1, %2;" : "=l"(r) : "l"(a), "l"(b));
    return r;
}
__device__ __forceinline__ float2 unpack2(ull v) {
    float2 f;
    asm("mov.b64 {%0, %1}, %2;" : "=f"(f.x), "=f"(f.y) : "l"(v));
    return f;
}

// ================= cursor zeroing (side stream) =================
__global__ void zero_cnt_kernel() {
    int i = blockIdx.x * blockDim.x + threadIdx.x;
    if (i < NN) g_cnt[i] = 0;
}

// ================= padded-bucket scatter: 4 edges/thread =================
__global__ __launch_bounds__(256) void scatter_kernel(
    const int4* __restrict__ src4, const int4* __restrict__ dst4)
{
    int i = blockIdx.x * blockDim.x + threadIdx.x;
    if (i >= EE / 4) return;
    int4 s4 = src4[i];
    int4 d4 = dst4[i];
    int i0 = atomicAdd(&g_cnt[d4.x], 1);
    int i1 = atomicAdd(&g_cnt[d4.y], 1);
    int i2 = atomicAdd(&g_cnt[d4.z], 1);
    int i3 = atomicAdd(&g_cnt[d4.w], 1);
    if (i0 < CAP) g_csr[d4.x * CAP + i0] = s4.x;
    if (i1 < CAP) g_csr[d4.y * CAP + i1] = s4.y;
    if (i2 < CAP) g_csr[d4.z * CAP + i2] = s4.z;
    if (i3 < CAP) g_csr[d4.w * CAP + i3] = s4.w;
}

// ================= layer1 projection =================
#define G1_XSTRIDE 132
#define G1_SMEM ((INCH * C1 + 128 * G1_XSTRIDE) * 4)
__global__ __launch_bounds__(512) void gemm1_kernel(
    const float* __restrict__ x, const float* __restrict__ W,
    const float* __restrict__ asrc, const float* __restrict__ adst)
{
    extern __shared__ float sm[];
    float* Ws = sm;
    float* xs = sm + INCH * C1;

    int tid = threadIdx.x;
    int tx = tid & 15;
    int ty = tid >> 4;
    int base = blockIdx.x * 128;

    const float4* W4 = (const float4*)W;
    float4* Ws4v = (float4*)Ws;
    #pragma unroll
    for (int i = tid; i < INCH * C1 / 4; i += 512) Ws4v[i] = W4[i];

    const float4* x4 = (const float4*)x;
    #pragma unroll
    for (int it = 0; it < 8; it++) {
        int f = it * 512 + tid;
        int n = f >> 5;
        int k4 = f & 31;
        float4 v = make_float4(0.f, 0.f, 0.f, 0.f);
        if (base + n < NN) v = x4[(size_t)(base + n) * 32 + k4];
        *(float4*)&xs[n * G1_XSTRIDE + k4 * 4] = v;
    }
    __syncthreads();

    float acc[4][4];
    #pragma unroll
    for (int i = 0; i < 4; i++)
        #pragma unroll
        for (int j = 0; j < 4; j++) acc[i][j] = 0.f;

    const float4* WsRow = (const float4*)Ws + tx;
    const float* xr0 = &xs[(ty * 4 + 0) * G1_XSTRIDE];
    const float* xr1 = &xs[(ty * 4 + 1) * G1_XSTRIDE];
    const float* xr2 = &xs[(ty * 4 + 2) * G1_XSTRIDE];
    const float* xr3 = &xs[(ty * 4 + 3) * G1_XSTRIDE];

    #pragma unroll 8
    for (int k = 0; k < INCH; k++) {
        float4 w = WsRow[k * 16];
        float x0 = xr0[k], x1 = xr1[k], x2 = xr2[k], x3 = xr3[k];
        acc[0][0] = fmaf(x0, w.x, acc[0][0]); acc[0][1] = fmaf(x0, w.y, acc[0][1]);
        acc[0][2] = fmaf(x0, w.z, acc[0][2]); acc[0][3] = fmaf(x0, w.w, acc[0][3]);
        acc[1][0] = fmaf(x1, w.x, acc[1][0]); acc[1][1] = fmaf(x1, w.y, acc[1][1]);
        acc[1][2] = fmaf(x1, w.z, acc[1][2]); acc[1][3] = fmaf(x1, w.w, acc[1][3]);
        acc[2][0] = fmaf(x2, w.x, acc[2][0]); acc[2][1] = fmaf(x2, w.y, acc[2][1]);
        acc[2][2] = fmaf(x2, w.z, acc[2][2]); acc[2][3] = fmaf(x2, w.w, acc[2][3]);
        acc[3][0] = fmaf(x3, w.x, acc[3][0]); acc[3][1] = fmaf(x3, w.y, acc[3][1]);
        acc[3][2] = fmaf(x3, w.z, acc[3][2]); acc[3][3] = fmaf(x3, w.w, acc[3][3]);
    }

    #pragma unroll
    for (int i = 0; i < 4; i++) {
        int node = base + ty * 4 + i;
        if (node < NN)
            *(float4*)&g_h1[(size_t)node * C1 + tx * 4] =
                make_float4(acc[i][0], acc[i][1], acc[i][2], acc[i][3]);
    }

    float as0 = asrc[tx * 4 + 0], as1 = asrc[tx * 4 + 1], as2 = asrc[tx * 4 + 2], as3 = asrc[tx * 4 + 3];
    float ad0 = adst[tx * 4 + 0], ad1 = adst[tx * 4 + 1], ad2 = adst[tx * 4 + 2], ad3 = adst[tx * 4 + 3];
    __syncthreads();
    float* redS = xs;
    float* redD = xs + 128 * 17;
    #pragma unroll
    for (int i = 0; i < 4; i++) {
        int nl = ty * 4 + i;
        float ps = acc[i][0] * as0 + acc[i][1] * as1 + acc[i][2] * as2 + acc[i][3] * as3;
        float pd = acc[i][0] * ad0 + acc[i][1] * ad1 + acc[i][2] * ad2 + acc[i][3] * ad3;
        redS[nl * 17 + tx] = ps;
        redD[nl * 17 + tx] = pd;
    }
    __syncthreads();
    if (tid < 128) {
        int node = base + tid;
        if (node < NN) {
            float s = 0.f, d = 0.f;
            #pragma unroll
            for (int t = 0; t < 16; t++) { s += redS[tid * 17 + t]; d += redD[tid * 17 + t]; }
            g_ls[node] = s;
            g_ld[node] = d;
        }
    }
}

// ================= layer1 aggregate: 2-phase (all ev in regs, shfl-fed loop) =================
__global__ __launch_bounds__(256) void agg1_kernel(const float* __restrict__ bias)
{
    int warp = (blockIdx.x * blockDim.x + threadIdx.x) >> 5;
    if (warp >= NN) return;
    int lane = threadIdx.x & 31;
    int g = lane >> 3, t = lane & 7;   // TPE=8, G=4

    int beg = warp * CAP;
    int deg = g_cnt[warp];
    deg = deg < CAP ? deg : CAP;
    float ldv = g_ld[warp];

    // phase 1: whole bucket's indices + ev in registers (slots lane, lane+32)
    int s0 = 0, s1 = 0;
    float ev0 = 0.f, ev1 = 0.f;
    if (lane < deg) {
        s0 = g_csr[beg + lane];
        float l = g_ls[s0] + ldv;
        l = l > 0.f ? l : SLOPE * l;
        ev0 = __expf(l);
    }
    if (32 + lane < deg) {
        s1 = g_csr[beg + 32 + lane];
        float l = g_ls[s1] + ldv;
        l = l > 0.f ? l : SLOPE * l;
        ev1 = __expf(l);
    }
    float den = ev0 + ev1;
    #pragma unroll
    for (int off = 16; off > 0; off >>= 1)
        den += __shfl_xor_sync(0xffffffffu, den, off);

    // phase 2: pure-gather loop; s/ev come from shuffles (no dependent loads)
    ull acc[4] = {0ull, 0ull, 0ull, 0ull};
    #pragma unroll 2
    for (int base = 0; base < deg; base += 4) {
        int e = base + g;                         // stays within one 32-slot block
        int which = base >> 5;                    // warp-uniform
        int sv = which ? s1 : s0;
        float evv = which ? ev1 : ev0;
        int s = __shfl_sync(0xffffffffu, sv, e & 31);
        float ev = __shfl_sync(0xffffffffu, evv, e & 31);
        if (e < deg) {
            const ulonglong2* hp = (const ulonglong2*)(g_h1 + (size_t)s * C1 + t * 8);
            ulonglong2 A = hp[0], B = hp[1];
            ull ev2 = pack2(ev);
            fma2(acc[0], A.x, ev2);
            fma2(acc[1], A.y, ev2);
            fma2(acc[2], B.x, ev2);
            fma2(acc[3], B.y, ev2);
        }
    }

    // reduce across the 4 edge-groups (offsets 8, 16)
    #pragma unroll
    for (int off = 8; off < 32; off <<= 1)
        #pragma unroll
        for (int j = 0; j < 4; j++)
            acc[j] = add2(acc[j], __shfl_xor_sync(0xffffffffu, acc[j], off));

    if (g == 0) {
        float inv = den > 0.f ? 1.f / den : 0.f;
        __half2 o[4];
        #pragma unroll
        for (int j = 0; j < 4; j++) {
            float2 f = unpack2(acc[j]);
            float a = fmaxf(f.x * inv + bias[t * 8 + 2 * j + 0], 0.f);
            float b = fmaxf(f.y * inv + bias[t * 8 + 2 * j + 1], 0.f);
            o[j] = __float22half2_rn(make_float2(a, b));
        }
        *(uint4*)&g_z1[(size_t)warp * C1 + t * 8] = *(uint4*)o;
    }
}

// ================= layer2 projection: 4 nodes x 4 ch per thread =================
#define G2_XSTRIDE 68
__global__ __launch_bounds__(256) void gemm2_kernel(
    const float* __restrict__ W,
    const float* __restrict__ asrc, const float* __restrict__ adst)
{
    __shared__ float Ws[C1 * C2];
    __shared__ float xs[128 * G2_XSTRIDE];

    int tid = threadIdx.x;
    int tx = tid & 7;
    int ty = tid >> 3;
    int base = blockIdx.x * 128;

    for (int i = tid; i < C1 * C2; i += 256) Ws[i] = W[i];

    const uint4* z4 = (const uint4*)g_z1;
    #pragma unroll
    for (int it = 0; it < 4; it++) {
        int f = it * 256 + tid;
        int n = f >> 3, k8 = f & 7;
        int node = base + n;
        uint4 hv = make_uint4(0u, 0u, 0u, 0u);
        if (node < NN) hv = z4[(size_t)node * 8 + k8];
        const __half2* hp = (const __half2*)&hv;
        float* dstp = &xs[n * G2_XSTRIDE + k8 * 8];
        #pragma unroll
        for (int j = 0; j < 4; j++) {
            float2 f2 = __half22float2(hp[j]);
            dstp[2 * j + 0] = f2.x;
            dstp[2 * j + 1] = f2.y;
        }
    }
    __syncthreads();

    float acc[4][4];
    #pragma unroll
    for (int i = 0; i < 4; i++)
        #pragma unroll
        for (int j = 0; j < 4; j++) acc[i][j] = 0.f;

    const float4* WsRow = (const float4*)Ws + tx;
    const float* xr0 = &xs[(ty * 4 + 0) * G2_XSTRIDE];
    const float* xr1 = &xs[(ty * 4 + 1) * G2_XSTRIDE];
    const float* xr2 = &xs[(ty * 4 + 2) * G2_XSTRIDE];
    const float* xr3 = &xs[(ty * 4 + 3) * G2_XSTRIDE];

    #pragma unroll 8
    for (int k = 0; k < C1; k++) {
        float4 w = WsRow[k * 8];
        float x0 = xr0[k], x1 = xr1[k], x2 = xr2[k], x3 = xr3[k];
        acc[0][0] = fmaf(x0, w.x, acc[0][0]); acc[0][1] = fmaf(x0, w.y, acc[0][1]);
        acc[0][2] = fmaf(x0, w.z, acc[0][2]); acc[0][3] = fmaf(x0, w.w, acc[0][3]);
        acc[1][0] = fmaf(x1, w.x, acc[1][0]); acc[1][1] = fmaf(x1, w.y, acc[1][1]);
        acc[1][2] = fmaf(x1, w.z, acc[1][2]); acc[1][3] = fmaf(x1, w.w, acc[1][3]);
        acc[2][0] = fmaf(x2, w.x, acc[2][0]); acc[2][1] = fmaf(x2, w.y, acc[2][1]);
        acc[2][2] = fmaf(x2, w.z, acc[2][2]); acc[2][3] = fmaf(x2, w.w, acc[2][3]);
        acc[3][0] = fmaf(x3, w.x, acc[3][0]); acc[3][1] = fmaf(x3, w.y, acc[3][1]);
        acc[3][2] = fmaf(x3, w.z, acc[3][2]); acc[3][3] = fmaf(x3, w.w, acc[3][3]);
    }

    #pragma unroll
    for (int i = 0; i < 4; i++) {
        int node = base + ty * 4 + i;
        if (node < NN)
            *(float4*)&g_h2[(size_t)node * C2 + tx * 4] =
                make_float4(acc[i][0], acc[i][1], acc[i][2], acc[i][3]);
    }

    float as0 = asrc[tx * 4 + 0], as1 = asrc[tx * 4 + 1], as2 = asrc[tx * 4 + 2], as3 = asrc[tx * 4 + 3];
    float ad0 = adst[tx * 4 + 0], ad1 = adst[tx * 4 + 1], ad2 = adst[tx * 4 + 2], ad3 = adst[tx * 4 + 3];
    __syncthreads();
    float* redS = xs;
    float* redD = xs + 128 * 9;
    #pragma unroll
    for (int i = 0; i < 4; i++) {
        int nl = ty * 4 + i;
        float ps = acc[i][0] * as0 + acc[i][1] * as1 + acc[i][2] * as2 + acc[i][3] * as3;
        float pd = acc[i][0] * ad0 + acc[i][1] * ad1 + acc[i][2] * ad2 + acc[i][3] * ad3;
        redS[nl * 9 + tx] = ps;
        redD[nl * 9 + tx] = pd;
    }
    __syncthreads();
    if (tid < 128) {
        int node = base + tid;
        if (node < NN) {
            float s = 0.f, d = 0.f;
            #pragma unroll
            for (int t = 0; t < 8; t++) { s += redS[tid * 9 + t]; d += redD[tid * 9 + t]; }
            g_ls[node] = s;
            g_ld[node] = d;
        }
    }
}

// ================= layer2 aggregate: 2-phase -> output =================
__global__ __launch_bounds__(256) void agg2_kernel(
    const float* __restrict__ bias, float* __restrict__ out)
{
    int warp = (blockIdx.x * blockDim.x + threadIdx.x) >> 5;
    if (warp >= NN) return;
    int lane = threadIdx.x & 31;
    int g = lane >> 2, t = lane & 3;   // TPE=4, G=8

    int beg = warp * CAP;
    int deg = g_cnt[warp];
    deg = deg < CAP ? deg : CAP;
    float ldv = g_ld[warp];

    int s0 = 0, s1 = 0;
    float ev0 = 0.f, ev1 = 0.f;
    if (lane < deg) {
        s0 = g_csr[beg + lane];
        float l = g_ls[s0] + ldv;
        l = l > 0.f ? l : SLOPE * l;
        ev0 = __expf(l);
    }
    if (32 + lane < deg) {
        s1 = g_csr[beg + 32 + lane];
        float l = g_ls[s1] + ldv;
        l = l > 0.f ? l : SLOPE * l;
        ev1 = __expf(l);
    }
    float den = ev0 + ev1;
    #pragma unroll
    for (int off = 16; off > 0; off >>= 1)
        den += __shfl_xor_sync(0xffffffffu, den, off);

    ull acc[4] = {0ull, 0ull, 0ull, 0ull};
    #pragma unroll 2
    for (int base = 0; base < deg; base += 8) {
        int e = base + g;
        int which = base >> 5;
        int sv = which ? s1 : s0;
        float evv = which ? ev1 : ev0;
        int s = __shfl_sync(0xffffffffu, sv, e & 31);
        float ev = __shfl_sync(0xffffffffu, evv, e & 31);
        if (e < deg) {
            const ulonglong2* hp = (const ulonglong2*)(g_h2 + (size_t)s * C2 + t * 8);
            ulonglong2 A = hp[0], B = hp[1];
            ull ev2 = pack2(ev);
            fma2(acc[0], A.x, ev2);
            fma2(acc[1], A.y, ev2);
            fma2(acc[2], B.x, ev2);
            fma2(acc[3], B.y, ev2);
        }
    }

    #pragma unroll
    for (int off = 4; off < 32; off <<= 1)
        #pragma unroll
        for (int j = 0; j < 4; j++)
            acc[j] = add2(acc[j], __shfl_xor_sync(0xffffffffu, acc[j], off));

    if (g == 0) {
        float inv = den > 0.f ? 1.f / den : 0.f;
        float2 f0 = unpack2(acc[0]), f1 = unpack2(acc[1]);
        float2 f2 = unpack2(acc[2]), f3 = unpack2(acc[3]);
        float4 v0, v1;
        v0.x = f0.x * inv + bias[t * 8 + 0];
        v0.y = f0.y * inv + bias[t * 8 + 1];
        v0.z = f1.x * inv + bias[t * 8 + 2];
        v0.w = f1.y * inv + bias[t * 8 + 3];
        v1.x = f2.x * inv + bias[t * 8 + 4];
        v1.y = f2.y * inv + bias[t * 8 + 5];
        v1.z = f3.x * inv + bias[t * 8 + 6];
        v1.w = f3.y * inv + bias[t * 8 + 7];
        *(float4*)&out[(size_t)warp * C2 + t * 8 + 0] = v0;
        *(float4*)&out[(size_t)warp * C2 + t * 8 + 4] = v1;
    }
}

extern "C" void kernel_launch(void* const* d_in, const int* in_sizes, int n_in,
                              void* d_out, int out_size)
{
    const float* x   = (const float*)d_in[0];
    const int*   ei  = (const int*)d_in[1];
    const float* W1  = (const float*)d_in[2];
    const float* as1 = (const float*)d_in[3];
    const float* ad1 = (const float*)d_in[4];
    const float* b1  = (const float*)d_in[5];
    const float* W2  = (const float*)d_in[6];
    const float* as2 = (const float*)d_in[7];
    const float* ad2 = (const float*)d_in[8];
    const float* b2  = (const float*)d_in[9];
    const int* src = ei;
    const int* dst = ei + EE;

    static cudaStream_t s2 = nullptr;
    static cudaEvent_t evFork = nullptr, evJoin = nullptr;
    if (!s2) {
        cudaStreamCreateWithFlags(&s2, cudaStreamNonBlocking);
        cudaEventCreateWithFlags(&evFork, cudaEventDisableTiming);
        cudaEventCreateWithFlags(&evJoin, cudaEventDisableTiming);
        cudaFuncSetAttribute(gemm1_kernel, cudaFuncAttributeMaxDynamicSharedMemorySize, G1_SMEM);
    }

    const int T = 256;

    // fork: CSR build on s2 (independent of gemm1)
    cudaEventRecord(evFork, 0);
    cudaStreamWaitEvent(s2, evFork, 0);
    zero_cnt_kernel<<<(NN + 1023) / 1024, 1024, 0, s2>>>();
    scatter_kernel<<<(EE / 4 + T - 1) / T, T, 0, s2>>>((const int4*)src, (const int4*)dst);
    cudaEventRecord(evJoin, s2);

    // main stream: layer1 projection overlaps CSR build
    gemm1_kernel<<<(NN + 127) / 128, 512, G1_SMEM>>>(x, W1, as1, ad1);

    // join: aggregate needs both gemm1 outputs and the CSR
    cudaStreamWaitEvent(0, evJoin, 0);
    agg1_kernel<<<(NN * 32 + T - 1) / T, T>>>(b1);
    gemm2_kernel<<<(NN + 127) / 128, T>>>(W2, as2, ad2);
    agg2_kernel<<<(NN * 32 + T - 1) / T, T>>>(b2, (float*)d_out);
}